// round 10
// baseline (speedup 1.0000x reference)
#include <cuda_runtime.h>
#include <cuda_bf16.h>
#include <cstdint>

// LSTM decoder: B=1024, H=128, O=7, T=512.
// gates = h @ (W_ih+W_hh)^T + (b_ih+b_hh)
// 128 blocks x 128 threads (R3 base). Thread t owns unit u=t, all 4 gates,
// all 8 rows. REUSE-ORDERED FMA: groups of 8 consecutive fma.rn.f32x2 sharing
// the same weight operand (src2 reuse-cache hit -> target rt 2/SMSP).
// Double-buffered per-k4 operand prefetch (h-pairs + smem weights 1 ahead,
// o-gate LDG 2 ahead). One sync per step.

#define B_TOTAL   1024
#define HID       128
#define GATES     512
#define T_STEPS   512
#define OUT_DIM   7
#define ROWS      8
#define NBLOCKS   (B_TOTAL / ROWS)   // 128
#define TPB       128

__device__ float4 g_W[32 * GATES];   // [k4][g] combined transposed weights, 256 KB
__device__ float  g_bias[GATES];

// ---------- helpers ----------
__device__ __forceinline__ void ffma2(unsigned long long& d,
                                      unsigned long long a,
                                      unsigned long long b) {
    asm("fma.rn.f32x2 %0, %1, %2, %0;" : "+l"(d) : "l"(a), "l"(b));
}
__device__ __forceinline__ unsigned long long pack_bias(float b) {
    unsigned long long v;
    asm("mov.b64 %0, {%1, %2};" : "=l"(v) : "f"(b), "f"(0.0f));
    return v;
}
__device__ __forceinline__ float pairsum(unsigned long long v) {
    float a, b;
    asm("mov.b64 {%0, %1}, %2;" : "=f"(a), "=f"(b) : "l"(v));
    return a + b;
}
__device__ __forceinline__ float sigf(float x) {
    return __fdividef(1.0f, 1.0f + __expf(-x));
}
__device__ __forceinline__ float tanh_fast(float x) {
    return __fdividef(2.0f, 1.0f + __expf(-2.0f * x)) - 1.0f;
}

// ---------- prep ----------
__global__ void prep_kernel(const float* __restrict__ Wih,
                            const float* __restrict__ Whh,
                            const float* __restrict__ bih,
                            const float* __restrict__ bhh) {
    int idx = blockIdx.x * blockDim.x + threadIdx.x;
    if (idx < 32 * GATES) {
        int g  = idx & (GATES - 1);
        int k4 = idx >> 9;
        int base = g * HID + k4 * 4;
        float4 v;
        v.x = Wih[base + 0] + Whh[base + 0];
        v.y = Wih[base + 1] + Whh[base + 1];
        v.z = Wih[base + 2] + Whh[base + 2];
        v.w = Wih[base + 3] + Whh[base + 3];
        g_W[k4 * GATES + g] = v;
    }
    if (idx < GATES) g_bias[idx] = bih[idx] + bhh[idx];
}

// ---------- SMEM layout (floats) ----------
#define SW_F4       (32 * 384)                    // 12288 float4 : gates i,f,g (192 KB)
#define SH_OFF_F    (SW_F4 * 4)                   // 49152 : h double buffer 2*8*128 (8 KB)
#define SWOUT_OFF_F (SH_OFF_F + 2 * ROWS * HID)   // 51200 : float4[7][33]
#define SMEM_BYTES  ((SWOUT_OFF_F + OUT_DIM * 33 * 4) * 4)   // 208496

__global__ void __launch_bounds__(TPB, 1)
lstm_kernel(const float* __restrict__ ctx,
            const float* __restrict__ Wout,
            const float* __restrict__ bout,
            float* __restrict__ out) {
    extern __shared__ float smem[];
    float4* s_w    = reinterpret_cast<float4*>(smem);
    float*  s_h    = smem + SH_OFF_F;
    float4* s_wout = reinterpret_cast<float4*>(smem + SWOUT_OFF_F);

    const int t   = threadIdx.x;   // hidden unit
    const int blk = blockIdx.x;

    // stage W (i,f,g) into shared
    for (int i = t; i < SW_F4; i += TPB) {
        int k4 = i / 384;
        int g  = i - k4 * 384;
        s_w[i] = g_W[k4 * GATES + g];
    }
    // stage W_out (padded pitch 33)
    const float4* Wout4 = reinterpret_cast<const float4*>(Wout);
    for (int i = t; i < OUT_DIM * 32; i += TPB) {
        int o = i / 32, kk = i - o * 32;
        s_wout[o * 33 + kk] = Wout4[o * 32 + kk];
    }
    // h0 = ctx[b][255][:]
    for (int r = 0; r < ROWS; r++) {
        int b = blk * ROWS + r;
        s_h[r * HID + t] = ctx[((size_t)b * 256 + 255) * HID + t];
    }

    // biases of unit t's 4 gates, packed for accumulator init
    const unsigned long long bi = pack_bias(g_bias[t]);
    const unsigned long long bf = pack_bias(g_bias[HID + t]);
    const unsigned long long bg = pack_bias(g_bias[2 * HID + t]);
    const unsigned long long bo = pack_bias(g_bias[3 * HID + t]);

    // o-gate L2 stream base (row pitch GATES ulonglong2 per k4)
    const ulonglong2* __restrict__ wO =
        reinterpret_cast<const ulonglong2*>(&g_W[3 * HID + t]);

    // pred mapping: 56 threads spread over all warps
    const int pr = t >> 4;          // row 0..7
    const int po = t & 15;          // out idx, active if < 7
    const float bpred = (po < OUT_DIM) ? bout[po] : 0.0f;
    float* out_base = out + ((size_t)(blk * ROWS + pr) * T_STEPS) * OUT_DIM + po;

    float c[ROWS];
#pragma unroll
    for (int r = 0; r < ROWS; r++) c[r] = 0.0f;

    __syncthreads();

    int cur = 0;
    for (int s = 0; s < T_STEPS; s++) {
        const float* hc = s_h + cur * (ROWS * HID);
        float*       hn = s_h + (cur ^ 1) * (ROWS * HID);

        unsigned long long a0[ROWS], a1[ROWS], a2[ROWS], a3[ROWS];
#pragma unroll
        for (int r = 0; r < ROWS; r++) { a0[r] = bi; a1[r] = bf; a2[r] = bg; a3[r] = bo; }

        // double-buffered operands
        ulonglong2 hb[2][ROWS];     // h pairs for one k4, 8 rows
        ulonglong2 wb[2][3];        // w0,w1,w2 (smem)
        ulonglong2 w3b[2];          // o-gate (gmem, distance-2 prefetch)

        // prologue: k4=0 operands + o-gate k4=0,1
#pragma unroll
        for (int r = 0; r < ROWS; r++)
            hb[0][r] = *reinterpret_cast<const ulonglong2*>(hc + r * HID);
        wb[0][0] = *reinterpret_cast<const ulonglong2*>(&s_w[t]);
        wb[0][1] = *reinterpret_cast<const ulonglong2*>(&s_w[HID + t]);
        wb[0][2] = *reinterpret_cast<const ulonglong2*>(&s_w[2 * HID + t]);
        w3b[0] = __ldg(&wO[0]);
        w3b[1] = __ldg(&wO[(size_t)GATES]);

        // one k4 iteration: compute on buffer CB, load k4+1 into CB^1
#define K4_STEP(k4, CB)                                                          \
        {                                                                        \
            if ((k4) < 31) {                                                     \
                const int nk = (k4) + 1;                                         \
                wb[CB ^ 1][0] = *reinterpret_cast<const ulonglong2*>(&s_w[nk * 384 + t]);            \
                wb[CB ^ 1][1] = *reinterpret_cast<const ulonglong2*>(&s_w[nk * 384 + HID + t]);      \
                wb[CB ^ 1][2] = *reinterpret_cast<const ulonglong2*>(&s_w[nk * 384 + 2 * HID + t]);  \
                _Pragma("unroll")                                                \
                for (int r = 0; r < ROWS; r++)                                   \
                    hb[CB ^ 1][r] = *reinterpret_cast<const ulonglong2*>(hc + r * HID + nk * 4);     \
            }                                                                    \
            ulonglong2 w3 = w3b[(k4) & 1];                                       \
            if ((k4) + 2 < 32)                                                   \
                w3b[(k4) & 1] = __ldg(&wO[(size_t)((k4) + 2) * GATES]);          \
            /* reuse-ordered FMA: 8 consecutive FFMA2 share the same w operand */ \
            _Pragma("unroll")                                                    \
            for (int r = 0; r < ROWS; r++) ffma2(a0[r], hb[CB][r].x, wb[CB][0].x); \
            _Pragma("unroll")                                                    \
            for (int r = 0; r < ROWS; r++) ffma2(a0[r], hb[CB][r].y, wb[CB][0].y); \
            _Pragma("unroll")                                                    \
            for (int r = 0; r < ROWS; r++) ffma2(a1[r], hb[CB][r].x, wb[CB][1].x); \
            _Pragma("unroll")                                                    \
            for (int r = 0; r < ROWS; r++) ffma2(a1[r], hb[CB][r].y, wb[CB][1].y); \
            _Pragma("unroll")                                                    \
            for (int r = 0; r < ROWS; r++) ffma2(a2[r], hb[CB][r].x, wb[CB][2].x); \
            _Pragma("unroll")                                                    \
            for (int r = 0; r < ROWS; r++) ffma2(a2[r], hb[CB][r].y, wb[CB][2].y); \
            _Pragma("unroll")                                                    \
            for (int r = 0; r < ROWS; r++) ffma2(a3[r], hb[CB][r].x, w3.x);        \
            _Pragma("unroll")                                                    \
            for (int r = 0; r < ROWS; r++) ffma2(a3[r], hb[CB][r].y, w3.y);        \
        }

        for (int k4g = 0; k4g < 16; k4g++) {
            K4_STEP(2 * k4g,     0)
            K4_STEP(2 * k4g + 1, 1)
        }
#undef K4_STEP

        // LSTM elementwise — fully thread-local (8 rows)
#pragma unroll
        for (int r = 0; r < ROWS; r++) {
            float gi = pairsum(a0[r]);
            float gf = pairsum(a1[r]);
            float gg = pairsum(a2[r]);
            float go = pairsum(a3[r]);
            float iv = sigf(gi);
            float fv = sigf(gf);
            float gv = tanh_fast(gg);
            float ov = sigf(go);
            c[r] = fv * c[r] + iv * gv;
            hn[r * HID + t] = ov * tanh_fast(c[r]);
        }
        __syncthreads();

        // pred = h_new @ W_out^T + b_out  (56 threads; overlaps next GEMM)
        if (po < OUT_DIM) {
            const float4* hr = reinterpret_cast<const float4*>(hn + pr * HID);
            const float4* wr = s_wout + po * 33;
            float pa = 0.0f;
#pragma unroll 8
            for (int kk = 0; kk < 32; kk++) {
                float4 hv = hr[kk];
                float4 wv = wr[kk];
                pa += hv.x * wv.x + hv.y * wv.y + hv.z * wv.z + hv.w * wv.w;
            }
            out_base[(size_t)s * OUT_DIM] = pa + bpred;
        }
        cur ^= 1;
    }
}

extern "C" void kernel_launch(void* const* d_in, const int* in_sizes, int n_in,
                              void* d_out, int out_size) {
    const float* ctx  = (const float*)d_in[0];
    const float* Wih  = (const float*)d_in[1];
    const float* Whh  = (const float*)d_in[2];
    const float* bih  = (const float*)d_in[3];
    const float* bhh  = (const float*)d_in[4];
    const float* Wout = (const float*)d_in[5];
    const float* bout = (const float*)d_in[6];
    float* out = (float*)d_out;

    cudaFuncSetAttribute(lstm_kernel, cudaFuncAttributeMaxDynamicSharedMemorySize, SMEM_BYTES);

    prep_kernel<<<64, 256>>>(Wih, Whh, bih, bhh);
    lstm_kernel<<<NBLOCKS, TPB, SMEM_BYTES>>>(ctx, Wout, bout, out);
}

// round 11
// speedup vs baseline: 1.0257x; 1.0257x over previous
#include <cuda_runtime.h>
#include <cuda_bf16.h>
#include <cstdint>

// LSTM decoder: B=1024, H=128, O=7, T=512.
// gates = h @ (W_ih+W_hh)^T + (b_ih+b_hh)
// Grid = 148 blocks (one per SM): 136 blocks x 7 rows + 12 blocks x 6 rows.
// Thread t owns unit u=t, all 4 gates, all NR rows. fp32x2 packed FMA
// (sm_100a: ~rt4/SMSP -> at the fp32 SIMT pipe floor; win comes from using
// all 148 SMs instead of 128). One sync per step, double-buffered h.
// Gates i,f,g weights in SMEM; o-gate streamed from L2 with 4-ahead prefetch.

#define B_TOTAL   1024
#define HID       128
#define GATES     512
#define T_STEPS   512
#define OUT_DIM   7
#define RMAX      7
#define NBLOCKS   148
#define NB7       136               // blocks with 7 rows (136*7 + 12*6 = 1024)
#define TPB       128

__device__ float4 g_W[32 * GATES];   // [k4][g] combined transposed weights, 256 KB
__device__ float  g_bias[GATES];

// ---------- helpers ----------
__device__ __forceinline__ void ffma2(unsigned long long& d,
                                      unsigned long long a,
                                      unsigned long long b) {
    asm("fma.rn.f32x2 %0, %1, %2, %0;" : "+l"(d) : "l"(a), "l"(b));
}
__device__ __forceinline__ unsigned long long pack_bias(float b) {
    unsigned long long v;
    asm("mov.b64 %0, {%1, %2};" : "=l"(v) : "f"(b), "f"(0.0f));
    return v;
}
__device__ __forceinline__ float pairsum(unsigned long long v) {
    float a, b;
    asm("mov.b64 {%0, %1}, %2;" : "=f"(a), "=f"(b) : "l"(v));
    return a + b;
}
__device__ __forceinline__ float sigf(float x) {
    return __fdividef(1.0f, 1.0f + __expf(-x));
}
__device__ __forceinline__ float tanh_fast(float x) {
    return __fdividef(2.0f, 1.0f + __expf(-2.0f * x)) - 1.0f;
}

// ---------- prep ----------
__global__ void prep_kernel(const float* __restrict__ Wih,
                            const float* __restrict__ Whh,
                            const float* __restrict__ bih,
                            const float* __restrict__ bhh) {
    int idx = blockIdx.x * blockDim.x + threadIdx.x;
    if (idx < 32 * GATES) {
        int g  = idx & (GATES - 1);
        int k4 = idx >> 9;
        int base = g * HID + k4 * 4;
        float4 v;
        v.x = Wih[base + 0] + Whh[base + 0];
        v.y = Wih[base + 1] + Whh[base + 1];
        v.z = Wih[base + 2] + Whh[base + 2];
        v.w = Wih[base + 3] + Whh[base + 3];
        g_W[k4 * GATES + g] = v;
    }
    if (idx < GATES) g_bias[idx] = bih[idx] + bhh[idx];
}

// ---------- SMEM layout (floats) ----------
#define SW_F4       (32 * 384)                     // 12288 float4 : gates i,f,g (192 KB)
#define SH_OFF_F    (SW_F4 * 4)                    // 49152 : h double buffer 2*RMAX*128
#define SWOUT_OFF_F (SH_OFF_F + 2 * RMAX * HID)    // 49152 + 1792 = 50944
#define SMEM_BYTES  ((SWOUT_OFF_F + OUT_DIM * 33 * 4) * 4)   // 207472

template<int NR>
__device__ __forceinline__ void lstm_body(const float* __restrict__ ctx,
                                          const float* __restrict__ Wout,
                                          const float* __restrict__ bout,
                                          float* __restrict__ out,
                                          int row_base) {
    extern __shared__ float smem[];
    float4* s_w    = reinterpret_cast<float4*>(smem);
    float*  s_h    = smem + SH_OFF_F;
    float4* s_wout = reinterpret_cast<float4*>(smem + SWOUT_OFF_F);

    const int t = threadIdx.x;   // hidden unit

    // stage W (i,f,g) into shared
    for (int i = t; i < SW_F4; i += TPB) {
        int k4 = i / 384;
        int g  = i - k4 * 384;
        s_w[i] = g_W[k4 * GATES + g];
    }
    // stage W_out (padded pitch 33)
    const float4* Wout4 = reinterpret_cast<const float4*>(Wout);
    for (int i = t; i < OUT_DIM * 32; i += TPB) {
        int o = i / 32, kk = i - o * 32;
        s_wout[o * 33 + kk] = Wout4[o * 32 + kk];
    }
    // h0 = ctx[b][255][:]
#pragma unroll
    for (int r = 0; r < NR; r++) {
        int b = row_base + r;
        s_h[r * HID + t] = ctx[((size_t)b * 256 + 255) * HID + t];
    }

    // biases of unit t's 4 gates, packed for accumulator init
    const unsigned long long bi = pack_bias(g_bias[t]);
    const unsigned long long bf = pack_bias(g_bias[HID + t]);
    const unsigned long long bg = pack_bias(g_bias[2 * HID + t]);
    const unsigned long long bo = pack_bias(g_bias[3 * HID + t]);

    // o-gate L2 stream base (row pitch GATES ulonglong2 per k4)
    const ulonglong2* __restrict__ wO =
        reinterpret_cast<const ulonglong2*>(&g_W[3 * HID + t]);

    // pred mapping: thread groups of 16 -> one row each, 7 active lanes
    const int pr = t >> 4;          // row 0..7
    const int po = t & 15;          // out idx, active if < 7
    const bool do_pred = (po < OUT_DIM) && (pr < NR);
    const float bpred = do_pred ? bout[po] : 0.0f;
    float* out_base = out + ((size_t)(row_base + pr) * T_STEPS) * OUT_DIM + po;

    float c[NR];
#pragma unroll
    for (int r = 0; r < NR; r++) c[r] = 0.0f;

    __syncthreads();

    int cur = 0;
    for (int s = 0; s < T_STEPS; s++) {
        const float* hc = s_h + cur * (RMAX * HID);
        float*       hn = s_h + (cur ^ 1) * (RMAX * HID);

        unsigned long long a0[NR], a1[NR], a2[NR], a3[NR];
#pragma unroll
        for (int r = 0; r < NR; r++) { a0[r] = bi; a1[r] = bf; a2[r] = bg; a3[r] = bo; }

        // o-gate prefetch pipeline: group of 4 k4-rows ahead
        ulonglong2 w3buf[4];
#pragma unroll
        for (int j = 0; j < 4; j++) w3buf[j] = __ldg(&wO[(size_t)j * GATES]);

#pragma unroll 4
        for (int k4 = 0; k4 < 32; k4++) {
            ulonglong2 w0 = *reinterpret_cast<const ulonglong2*>(&s_w[k4 * 384 + t]);
            ulonglong2 w1 = *reinterpret_cast<const ulonglong2*>(&s_w[k4 * 384 + HID + t]);
            ulonglong2 w2 = *reinterpret_cast<const ulonglong2*>(&s_w[k4 * 384 + 2 * HID + t]);
            ulonglong2 w3 = w3buf[k4 & 3];
            if ((k4 & 3) == 3 && k4 + 1 < 32) {
#pragma unroll
                for (int j = 0; j < 4; j++)
                    w3buf[j] = __ldg(&wO[(size_t)(k4 + 1 + j) * GATES]);
            }
#pragma unroll
            for (int r = 0; r < NR; r++) {
                ulonglong2 h2 = *reinterpret_cast<const ulonglong2*>(hc + r * HID + k4 * 4); // bcast
                ffma2(a0[r], h2.x, w0.x); ffma2(a0[r], h2.y, w0.y);
                ffma2(a1[r], h2.x, w1.x); ffma2(a1[r], h2.y, w1.y);
                ffma2(a2[r], h2.x, w2.x); ffma2(a2[r], h2.y, w2.y);
                ffma2(a3[r], h2.x, w3.x); ffma2(a3[r], h2.y, w3.y);
            }
        }

        // LSTM elementwise — fully thread-local (NR rows)
#pragma unroll
        for (int r = 0; r < NR; r++) {
            float gi = pairsum(a0[r]);
            float gf = pairsum(a1[r]);
            float gg = pairsum(a2[r]);
            float go = pairsum(a3[r]);
            float iv = sigf(gi);
            float fv = sigf(gf);
            float gv = tanh_fast(gg);
            float ov = sigf(go);
            c[r] = fv * c[r] + iv * gv;
            hn[r * HID + t] = ov * tanh_fast(c[r]);
        }
        __syncthreads();

        // pred = h_new @ W_out^T + b_out  (<=49 active threads; overlaps next GEMM)
        if (do_pred) {
            const float4* hr = reinterpret_cast<const float4*>(hn + pr * HID);
            const float4* wr = s_wout + po * 33;
            float pa = 0.0f;
#pragma unroll 8
            for (int kk = 0; kk < 32; kk++) {
                float4 hv = hr[kk];
                float4 wv = wr[kk];
                pa += hv.x * wv.x + hv.y * wv.y + hv.z * wv.z + hv.w * wv.w;
            }
            out_base[(size_t)s * OUT_DIM] = pa + bpred;
        }
        cur ^= 1;
    }
}

__global__ void __launch_bounds__(TPB, 1)
lstm_kernel(const float* __restrict__ ctx,
            const float* __restrict__ Wout,
            const float* __restrict__ bout,
            float* __restrict__ out) {
    const int blk = blockIdx.x;
    if (blk < NB7) {
        lstm_body<7>(ctx, Wout, bout, out, blk * 7);
    } else {
        lstm_body<6>(ctx, Wout, bout, out, NB7 * 7 + (blk - NB7) * 6);
    }
}

extern "C" void kernel_launch(void* const* d_in, const int* in_sizes, int n_in,
                              void* d_out, int out_size) {
    const float* ctx  = (const float*)d_in[0];
    const float* Wih  = (const float*)d_in[1];
    const float* Whh  = (const float*)d_in[2];
    const float* bih  = (const float*)d_in[3];
    const float* bhh  = (const float*)d_in[4];
    const float* Wout = (const float*)d_in[5];
    const float* bout = (const float*)d_in[6];
    float* out = (float*)d_out;

    cudaFuncSetAttribute(lstm_kernel, cudaFuncAttributeMaxDynamicSharedMemorySize, SMEM_BYTES);

    prep_kernel<<<64, 256>>>(Wih, Whh, bih, bhh);
    lstm_kernel<<<NBLOCKS, TPB, SMEM_BYTES>>>(ctx, Wout, bout, out);
}

// round 12
// speedup vs baseline: 1.0737x; 1.0468x over previous
#include <cuda_runtime.h>
#include <cuda_bf16.h>
#include <cstdint>

// LSTM decoder: B=1024, H=128, O=7, T=512.
// gates = h @ (W_ih+W_hh)^T + (b_ih+b_hh)
// Grid = 148 blocks (one per SM): 136 x 7 rows + 12 x 6 rows. TPB=128.
// Thread t owns unit u=t, all 4 gates, all NR rows. fp32x2 packed FMA.
// o-gate streamed from L2 with DEPTH-8 ring prefetch (distance 8 k4 >> L2 lat).
// Pred GEMM for step s-1 executes in the latency shadow of step s's prologue
// LDGs (h_cur == h_new of s-1). One sync per step, double-buffered h.

#define B_TOTAL   1024
#define HID       128
#define GATES     512
#define T_STEPS   512
#define OUT_DIM   7
#define RMAX      7
#define NBLOCKS   148
#define NB7       136               // blocks with 7 rows (136*7 + 12*6 = 1024)
#define TPB       128

__device__ float4 g_W[32 * GATES];   // [k4][g] combined transposed weights, 256 KB
__device__ float  g_bias[GATES];

// ---------- helpers ----------
__device__ __forceinline__ void ffma2(unsigned long long& d,
                                      unsigned long long a,
                                      unsigned long long b) {
    asm("fma.rn.f32x2 %0, %1, %2, %0;" : "+l"(d) : "l"(a), "l"(b));
}
__device__ __forceinline__ unsigned long long pack_bias(float b) {
    unsigned long long v;
    asm("mov.b64 %0, {%1, %2};" : "=l"(v) : "f"(b), "f"(0.0f));
    return v;
}
__device__ __forceinline__ float pairsum(unsigned long long v) {
    float a, b;
    asm("mov.b64 {%0, %1}, %2;" : "=f"(a), "=f"(b) : "l"(v));
    return a + b;
}
__device__ __forceinline__ float sigf(float x) {
    return __fdividef(1.0f, 1.0f + __expf(-x));
}
__device__ __forceinline__ float tanh_fast(float x) {
    return __fdividef(2.0f, 1.0f + __expf(-2.0f * x)) - 1.0f;
}

// ---------- prep ----------
__global__ void prep_kernel(const float* __restrict__ Wih,
                            const float* __restrict__ Whh,
                            const float* __restrict__ bih,
                            const float* __restrict__ bhh) {
    int idx = blockIdx.x * blockDim.x + threadIdx.x;
    if (idx < 32 * GATES) {
        int g  = idx & (GATES - 1);
        int k4 = idx >> 9;
        int base = g * HID + k4 * 4;
        float4 v;
        v.x = Wih[base + 0] + Whh[base + 0];
        v.y = Wih[base + 1] + Whh[base + 1];
        v.z = Wih[base + 2] + Whh[base + 2];
        v.w = Wih[base + 3] + Whh[base + 3];
        g_W[k4 * GATES + g] = v;
    }
    if (idx < GATES) g_bias[idx] = bih[idx] + bhh[idx];
}

// ---------- SMEM layout (floats) ----------
#define SW_F4       (32 * 384)                     // 12288 float4 : gates i,f,g (192 KB)
#define SH_OFF_F    (SW_F4 * 4)                    // 49152 : h double buffer 2*RMAX*128
#define SWOUT_OFF_F (SH_OFF_F + 2 * RMAX * HID)    // 49152 + 1792 = 50944
#define SMEM_BYTES  ((SWOUT_OFF_F + OUT_DIM * 33 * 4) * 4)   // 207472

template<int NR>
__device__ __forceinline__ void lstm_body(const float* __restrict__ ctx,
                                          const float* __restrict__ Wout,
                                          const float* __restrict__ bout,
                                          float* __restrict__ out,
                                          int row_base) {
    extern __shared__ float smem[];
    float4* s_w    = reinterpret_cast<float4*>(smem);
    float*  s_h    = smem + SH_OFF_F;
    float4* s_wout = reinterpret_cast<float4*>(smem + SWOUT_OFF_F);

    const int t = threadIdx.x;   // hidden unit

    // stage W (i,f,g) into shared
    for (int i = t; i < SW_F4; i += TPB) {
        int k4 = i / 384;
        int g  = i - k4 * 384;
        s_w[i] = g_W[k4 * GATES + g];
    }
    // stage W_out (padded pitch 33)
    const float4* Wout4 = reinterpret_cast<const float4*>(Wout);
    for (int i = t; i < OUT_DIM * 32; i += TPB) {
        int o = i / 32, kk = i - o * 32;
        s_wout[o * 33 + kk] = Wout4[o * 32 + kk];
    }
    // h0 = ctx[b][255][:]
#pragma unroll
    for (int r = 0; r < NR; r++) {
        int b = row_base + r;
        s_h[r * HID + t] = ctx[((size_t)b * 256 + 255) * HID + t];
    }

    // biases of unit t's 4 gates, packed for accumulator init
    const unsigned long long bi = pack_bias(g_bias[t]);
    const unsigned long long bf = pack_bias(g_bias[HID + t]);
    const unsigned long long bg = pack_bias(g_bias[2 * HID + t]);
    const unsigned long long bo = pack_bias(g_bias[3 * HID + t]);

    // o-gate L2 stream base (row pitch GATES ulonglong2 per k4)
    const ulonglong2* __restrict__ wO =
        reinterpret_cast<const ulonglong2*>(&g_W[3 * HID + t]);

    // pred mapping: thread groups of 16 -> one row each, 7 active lanes
    const int pr = t >> 4;          // row 0..7
    const int po = t & 15;          // out idx, active if < 7
    const bool do_pred = (po < OUT_DIM) && (pr < NR);
    const float bpred = do_pred ? bout[po] : 0.0f;
    float* out_base = out + ((size_t)(row_base + pr) * T_STEPS) * OUT_DIM + po;

    float c[NR];
#pragma unroll
    for (int r = 0; r < NR; r++) c[r] = 0.0f;

    __syncthreads();

    int cur = 0;
    for (int s = 0; s < T_STEPS; s++) {
        const float* hc = s_h + cur * (RMAX * HID);
        float*       hn = s_h + (cur ^ 1) * (RMAX * HID);

        // ---- issue deep o-gate prefetch FIRST (8 LDGs in flight) ----
        ulonglong2 w3buf[8];
#pragma unroll
        for (int j = 0; j < 8; j++) w3buf[j] = __ldg(&wO[(size_t)j * GATES]);

        // ---- pred for step s-1 in the LDG latency shadow (hc = h_new of s-1) ----
        if (s > 0 && do_pred) {
            const float4* hr = reinterpret_cast<const float4*>(hc + pr * HID);
            const float4* wr = s_wout + po * 33;
            float pa = 0.0f;
#pragma unroll 8
            for (int kk = 0; kk < 32; kk++) {
                float4 hv = hr[kk];
                float4 wv = wr[kk];
                pa += hv.x * wv.x + hv.y * wv.y + hv.z * wv.z + hv.w * wv.w;
            }
            out_base[(size_t)(s - 1) * OUT_DIM] = pa + bpred;
        }

        unsigned long long a0[NR], a1[NR], a2[NR], a3[NR];
#pragma unroll
        for (int r = 0; r < NR; r++) { a0[r] = bi; a1[r] = bf; a2[r] = bg; a3[r] = bo; }

#pragma unroll 8
        for (int k4 = 0; k4 < 32; k4++) {
            ulonglong2 w0 = *reinterpret_cast<const ulonglong2*>(&s_w[k4 * 384 + t]);
            ulonglong2 w1 = *reinterpret_cast<const ulonglong2*>(&s_w[k4 * 384 + HID + t]);
            ulonglong2 w2 = *reinterpret_cast<const ulonglong2*>(&s_w[k4 * 384 + 2 * HID + t]);
            ulonglong2 w3 = w3buf[k4 & 7];
            if (k4 + 8 < 32)
                w3buf[k4 & 7] = __ldg(&wO[(size_t)(k4 + 8) * GATES]);   // distance-8 refill
#pragma unroll
            for (int r = 0; r < NR; r++) {
                ulonglong2 h2 = *reinterpret_cast<const ulonglong2*>(hc + r * HID + k4 * 4); // bcast
                ffma2(a0[r], h2.x, w0.x); ffma2(a0[r], h2.y, w0.y);
                ffma2(a1[r], h2.x, w1.x); ffma2(a1[r], h2.y, w1.y);
                ffma2(a2[r], h2.x, w2.x); ffma2(a2[r], h2.y, w2.y);
                ffma2(a3[r], h2.x, w3.x); ffma2(a3[r], h2.y, w3.y);
            }
        }

        // LSTM elementwise — fully thread-local (NR rows)
#pragma unroll
        for (int r = 0; r < NR; r++) {
            float gi = pairsum(a0[r]);
            float gf = pairsum(a1[r]);
            float gg = pairsum(a2[r]);
            float go = pairsum(a3[r]);
            float iv = sigf(gi);
            float fv = sigf(gf);
            float gv = tanh_fast(gg);
            float ov = sigf(go);
            c[r] = fv * c[r] + iv * gv;
            hn[r * HID + t] = ov * tanh_fast(c[r]);
        }
        __syncthreads();
        cur ^= 1;
    }

    // epilogue: pred for the final step (h_new lives in buffer `cur`)
    if (do_pred) {
        const float* hl = s_h + cur * (RMAX * HID);
        const float4* hr = reinterpret_cast<const float4*>(hl + pr * HID);
        const float4* wr = s_wout + po * 33;
        float pa = 0.0f;
#pragma unroll 8
        for (int kk = 0; kk < 32; kk++) {
            float4 hv = hr[kk];
            float4 wv = wr[kk];
            pa += hv.x * wv.x + hv.y * wv.y + hv.z * wv.z + hv.w * wv.w;
        }
        out_base[(size_t)(T_STEPS - 1) * OUT_DIM] = pa + bpred;
    }
}

__global__ void __launch_bounds__(TPB, 1)
lstm_kernel(const float* __restrict__ ctx,
            const float* __restrict__ Wout,
            const float* __restrict__ bout,
            float* __restrict__ out) {
    const int blk = blockIdx.x;
    if (blk < NB7) {
        lstm_body<7>(ctx, Wout, bout, out, blk * 7);
    } else {
        lstm_body<6>(ctx, Wout, bout, out, NB7 * 7 + (blk - NB7) * 6);
    }
}

extern "C" void kernel_launch(void* const* d_in, const int* in_sizes, int n_in,
                              void* d_out, int out_size) {
    const float* ctx  = (const float*)d_in[0];
    const float* Wih  = (const float*)d_in[1];
    const float* Whh  = (const float*)d_in[2];
    const float* bih  = (const float*)d_in[3];
    const float* bhh  = (const float*)d_in[4];
    const float* Wout = (const float*)d_in[5];
    const float* bout = (const float*)d_in[6];
    float* out = (float*)d_out;

    cudaFuncSetAttribute(lstm_kernel, cudaFuncAttributeMaxDynamicSharedMemorySize, SMEM_BYTES);

    prep_kernel<<<64, 256>>>(Wih, Whh, bih, bhh);
    lstm_kernel<<<NBLOCKS, TPB, SMEM_BYTES>>>(ctx, Wout, bout, out);
}